// round 4
// baseline (speedup 1.0000x reference)
#include <cuda_runtime.h>
#include <cuda_fp16.h>
#include <stdint.h>

#define IN_F   4096
#define OUT_F  11008
#define BATCH  16

#define K_CHUNKS 16
#define K_TASK   (IN_F / K_CHUNKS)     // 256 k per task
#define NT16     (K_TASK / 16)         // 16 k16-tiles per task
#define NTILES   (OUT_F / 8)           // 1376 n-tiles (8 channels each)

#define BLOCKS   148
#define THREADS  512

#define ROW_H      (IN_F + 8)
#define SMEM_BYTES (BATCH * ROW_H * 2)   // 131,328 B

__device__ __half   g_xh[BATCH * IN_F];
__device__ unsigned g_done;              // monotonic epoch barrier (never reset)
__device__ unsigned g_nt[K_CHUNKS];      // per-kchunk n-tile counters

extern __shared__ __half s_x[];

__global__ void __launch_bounds__(THREADS, 1)
fused_kernel(const float* __restrict__ x,
             const int*   __restrict__ W,
             const float* __restrict__ scale,
             const float* __restrict__ bias,
             float*       __restrict__ out) {
    const int tid = threadIdx.x;

    // ================= init phase (per replay) =================
    {
        float4 z = make_float4(0.f, 0.f, 0.f, 0.f);
        const int total4 = BATCH * OUT_F / 4;
        for (int i = blockIdx.x * THREADS + tid; i < total4; i += BLOCKS * THREADS)
            ((float4*)out)[i] = z;

        const int nh2 = BATCH * IN_F / 2;
        for (int i = blockIdx.x * THREADS + tid; i < nh2; i += BLOCKS * THREADS) {
            float2 v = ((const float2*)x)[i];
            ((__half2*)g_xh)[i] = __floats2half2_rn(v.x, v.y);
        }
        if (blockIdx.x == 0 && tid < K_CHUNKS) g_nt[tid] = 0u;
    }
    __threadfence();
    __syncthreads();
    // epoch spin barrier: all 148 blocks resident (1 CTA/SM), monotonic counter
    if (tid == 0) {
        unsigned my = atomicAdd(&g_done, 1u);
        unsigned target = (my / BLOCKS) * BLOCKS + BLOCKS;
        while (*((volatile unsigned*)&g_done) < target) __nanosleep(64);
    }
    __syncthreads();
    __threadfence();

    // ================= stage x into padded smem =================
    {
        const uint4* src = (const uint4*)g_xh;
        const int n128 = BATCH * IN_F / 8;
        for (int i = tid; i < n128; i += THREADS) {
            int r = i >> 9, c = i & 511;
            *(uint4*)&s_x[r * ROW_H + c * 8] = src[i];
        }
    }
    __syncthreads();

    const int lane = tid & 31;
    const int wid  = tid >> 5;
    const int kc   = (blockIdx.x * (THREADS / 32) + wid) & (K_CHUNKS - 1);
    const int k0   = kc * K_TASK;

    // ---- A fragments: resident in registers for the whole kernel ----
    unsigned afr[NT16][4];
    {
        unsigned smem_base = (unsigned)__cvta_generic_to_shared(s_x);
        unsigned a_off = (unsigned)((lane & 15) * (ROW_H * 2) + ((lane >> 4) & 1) * 16);
        #pragma unroll
        for (int j = 0; j < NT16; j++) {
            unsigned aaddr = smem_base + a_off + (unsigned)((k0 + j * 16) * 2);
            asm volatile(
                "ldmatrix.sync.aligned.m8n8.x4.shared.b16 {%0,%1,%2,%3}, [%4];"
                : "=r"(afr[j][0]), "=r"(afr[j][1]), "=r"(afr[j][2]), "=r"(afr[j][3])
                : "r"(aaddr));
        }
    }

    const int ng = lane >> 2;       // weight row within n-tile
    const int tq = lane & 3;        // k-quad
    const int sA = (lane & ~3) | (tq >> 1);   // shfl src for b0 pair
    const int sB = sA + 2;                    // shfl src for b1 pair
    const bool todd = (tq & 1);

    // ================= main work-stealing loop =================
    unsigned n;
    if (lane == 0) n = atomicAdd(&g_nt[kc], 1u);
    n = __shfl_sync(0xffffffffu, n, 0);

    if (n < NTILES) {
        const int4* wp = (const int4*)(W + (size_t)(n * 8 + ng) * IN_F + k0);
        int4 wb[2][4];
        #pragma unroll
        for (int i = 0; i < 4; i++) wb[0][i] = __ldg(wp + 4 * i + tq);

        for (;;) {
            // steal next task now: ATOMG latency hidden under this task
            unsigned n2;
            if (lane == 0) n2 = atomicAdd(&g_nt[kc], 1u);
            n2 = __shfl_sync(0xffffffffu, n2, 0);
            const int4* wp2 = (const int4*)(W + (size_t)(n2 * 8 + ng) * IN_F + k0);

            float c0 = 0.f, c1 = 0.f, c2 = 0.f, c3 = 0.f;

            #pragma unroll
            for (int g = 0; g < 4; g++) {
                // prefetch next 4-tile group (or next task's first group)
                if (g < 3) {
                    #pragma unroll
                    for (int i = 0; i < 4; i++)
                        wb[(g + 1) & 1][i] = __ldg(wp + 16 * (g + 1) + 4 * i + tq);
                } else if (n2 < NTILES) {
                    #pragma unroll
                    for (int i = 0; i < 4; i++)
                        wb[0][i] = __ldg(wp2 + 4 * i + tq);
                }

                #pragma unroll
                for (int i = 0; i < 4; i++) {
                    const int jt = g * 4 + i;
                    int4 w = wb[g & 1][i];
                    // lane holds row ng, k = 16*jt + 4*tq .. +3 (converted to fp16)
                    __half2 h01 = __halves2half2(__int2half_rn(w.x), __int2half_rn(w.y));
                    __half2 h23 = __halves2half2(__int2half_rn(w.z), __int2half_rn(w.w));
                    unsigned u01 = *reinterpret_cast<unsigned*>(&h01);
                    unsigned u23 = *reinterpret_cast<unsigned*>(&h23);
                    // redistribute to B-fragment layout
                    unsigned s1 = __shfl_sync(0xffffffffu, u01, sA);
                    unsigned s2 = __shfl_sync(0xffffffffu, u23, sA);
                    unsigned s3 = __shfl_sync(0xffffffffu, u01, sB);
                    unsigned s4 = __shfl_sync(0xffffffffu, u23, sB);
                    unsigned b0 = todd ? s2 : s1;
                    unsigned b1 = todd ? s4 : s3;

                    asm volatile(
                        "mma.sync.aligned.m16n8k16.row.col.f32.f16.f16.f32 "
                        "{%0,%1,%2,%3}, {%4,%5,%6,%7}, {%8,%9}, {%0,%1,%2,%3};"
                        : "+f"(c0), "+f"(c1), "+f"(c2), "+f"(c3)
                        : "r"(afr[jt][0]), "r"(afr[jt][1]),
                          "r"(afr[jt][2]), "r"(afr[jt][3]),
                          "r"(b0), "r"(b1));
                }
            }

            // ---- epilogue: scale (+bias on kc==0), reduce into out ----
            {
                const int o0 = (int)(n * 8) + tq * 2;
                const float s0 = __ldg(scale + o0);
                const float s1f = __ldg(scale + o0 + 1);
                float v0 = c0 * s0, v1 = c1 * s1f, v2 = c2 * s0, v3 = c3 * s1f;
                if (kc == 0) {
                    const float b0f = __ldg(bias + o0);
                    const float b1f = __ldg(bias + o0 + 1);
                    v0 += b0f; v1 += b1f; v2 += b0f; v3 += b1f;
                }
                atomicAdd(&out[(size_t)ng * OUT_F + o0],            v0);
                atomicAdd(&out[(size_t)ng * OUT_F + o0 + 1],        v1);
                atomicAdd(&out[(size_t)(ng + 8) * OUT_F + o0],      v2);
                atomicAdd(&out[(size_t)(ng + 8) * OUT_F + o0 + 1],  v3);
            }

            if (n2 >= NTILES) break;
            n = n2;
            wp = wp2;
        }
    }
}

// ---------------------------------------------------------------------------
extern "C" void kernel_launch(void* const* d_in, const int* in_sizes, int n_in,
                              void* d_out, int out_size) {
    const float* x     = (const float*)d_in[0];
    const int*   w     = (const int*)  d_in[1];
    const float* scale = (const float*)d_in[2];
    const float* bias  = (const float*)d_in[3];
    float*       out   = (float*)d_out;

    cudaFuncSetAttribute(fused_kernel,
                         cudaFuncAttributeMaxDynamicSharedMemorySize, SMEM_BYTES);

    fused_kernel<<<BLOCKS, THREADS, SMEM_BYTES>>>(x, w, scale, bias, out);
}

// round 5
// speedup vs baseline: 1.0457x; 1.0457x over previous
#include <cuda_runtime.h>
#include <cuda_fp16.h>
#include <stdint.h>

#define IN_F   4096
#define OUT_F  11008
#define BATCH  16

#define K_CHUNKS 16
#define K_TASK   (IN_F / K_CHUNKS)      // 256 k per task
#define NTILES   (OUT_F / 8)            // 1376 n-tiles (8 channels)
#define NTASKS   (NTILES * K_CHUNKS)    // 22016

#define BLOCKS   148
#define THREADS  512

#define ROW_H      (IN_F + 8)
#define SMEM_BYTES (BATCH * ROW_H * 2)  // 131,328 B

__device__ __half   g_xh[BATCH * IN_F];
__device__ unsigned g_ticket;

// ---------------------------------------------------------------------------
// Prologue: reset ticket, x fp32->fp16, out = bias (vectorized).
// ---------------------------------------------------------------------------
__global__ void prologue_kernel(const float* __restrict__ x,
                                const float* __restrict__ bias,
                                float* __restrict__ out) {
    const int i      = blockIdx.x * blockDim.x + threadIdx.x;
    const int stride = gridDim.x * blockDim.x;
    if (i == 0) g_ticket = 0u;

    const int nh2 = BATCH * IN_F / 2;
    for (int j = i; j < nh2; j += stride) {
        float2 v = ((const float2*)x)[j];
        ((__half2*)g_xh)[j] = __floats2half2_rn(v.x, v.y);
    }

    const float4* b4 = (const float4*)bias;
    const int total4 = BATCH * OUT_F / 4;
    const int row4   = OUT_F / 4;                 // 2752
    for (int j = i; j < total4; j += stride) {
        ((float4*)out)[j] = __ldg(b4 + (j % row4));
    }
}

// ---------------------------------------------------------------------------
// GEMM: persistent blocks, warp work-stealing, LDG.128 weights + shfl
// redistribution, double-buffer + cross-task prefetch + L2 prefetch.
// Task = 8 output channels x 256 K.
// ---------------------------------------------------------------------------
extern __shared__ __half s_x[];

__global__ void __launch_bounds__(THREADS, 1)
gemm_kernel(const int* __restrict__ W,
            const float* __restrict__ scale,
            float* __restrict__ out) {
    const int tid = threadIdx.x;

    // ---- stage x (fp16) into padded smem ----
    {
        const uint4* src = (const uint4*)g_xh;
        const int n128 = BATCH * IN_F / 8;
        for (int i = tid; i < n128; i += THREADS) {
            int r = i >> 9, c = i & 511;
            *(uint4*)&s_x[r * ROW_H + c * 8] = src[i];
        }
    }
    __syncthreads();

    const int lane = tid & 31;
    const int ng   = lane >> 2;                  // weight row within n-tile
    const int tq   = lane & 3;                   // k-quad
    const int sA   = (lane & ~3) | (tq >> 1);    // shfl src for b0 pair
    const int sB   = sA + 2;                     // shfl src for b1 pair
    const bool todd = (tq & 1);

    unsigned smem_base = (unsigned)__cvta_generic_to_shared(s_x);
    unsigned a_off = (unsigned)((lane & 15) * (ROW_H * 2) + ((lane >> 4) & 1) * 16);

    unsigned t;
    if (lane == 0) t = atomicAdd(&g_ticket, 1u);
    t = __shfl_sync(0xffffffffu, t, 0);
    if (t >= NTASKS) return;

    int   n  = (int)(t % NTILES);
    int   k0 = (int)(t / NTILES) * K_TASK;
    const int4* wp = (const int4*)(W + (size_t)(n * 8 + ng) * IN_F + k0);

    int4 bufA[8], bufB[8];
    #pragma unroll
    for (int i = 0; i < 8; i++) bufA[i] = __ldg(wp + 4 * i + tq);

    for (;;) {
        // steal next task now (latency hidden under this task)
        unsigned t2;
        if (lane == 0) t2 = atomicAdd(&g_ticket, 1u);
        t2 = __shfl_sync(0xffffffffu, t2, 0);

        int n2 = 0, k02 = 0;
        const int4* wp2 = wp;
        const bool has2 = (t2 < NTASKS);
        if (has2) {
            n2  = (int)(t2 % NTILES);
            k02 = (int)(t2 / NTILES) * K_TASK;
            wp2 = (const int4*)(W + (size_t)(n2 * 8 + ng) * IN_F + k02);
            // L2-prefetch next task's full 8KB (2 x 128B lines per lane)
            const char* pb = (const char*)wp2 + (size_t)tq * 256;
            asm volatile("prefetch.global.L2 [%0];"       :: "l"(pb));
            asm volatile("prefetch.global.L2 [%0+128];"   :: "l"(pb));
        }

        float c0 = 0.f, c1 = 0.f, c2 = 0.f, c3 = 0.f;

        // load group 1 (tiles 8..15) into bufB
        #pragma unroll
        for (int i = 0; i < 8; i++) bufB[i] = __ldg(wp + 32 + 4 * i + tq);

        // ---- compute group 0 from bufA ----
        #pragma unroll
        for (int i = 0; i < 8; i++) {
            unsigned a0, a1, a2, a3;
            unsigned aaddr = smem_base + a_off + (unsigned)((k0 + i * 16) * 2);
            asm volatile(
                "ldmatrix.sync.aligned.m8n8.x4.shared.b16 {%0,%1,%2,%3}, [%4];"
                : "=r"(a0), "=r"(a1), "=r"(a2), "=r"(a3) : "r"(aaddr));

            int4 w = bufA[i];
            __half2 h01 = __halves2half2(__int2half_rn(w.x), __int2half_rn(w.y));
            __half2 h23 = __halves2half2(__int2half_rn(w.z), __int2half_rn(w.w));
            unsigned u01 = *reinterpret_cast<unsigned*>(&h01);
            unsigned u23 = *reinterpret_cast<unsigned*>(&h23);
            unsigned s1 = __shfl_sync(0xffffffffu, u01, sA);
            unsigned s2 = __shfl_sync(0xffffffffu, u23, sA);
            unsigned s3 = __shfl_sync(0xffffffffu, u01, sB);
            unsigned s4 = __shfl_sync(0xffffffffu, u23, sB);
            unsigned b0 = todd ? s2 : s1;
            unsigned b1 = todd ? s4 : s3;

            asm volatile(
                "mma.sync.aligned.m16n8k16.row.col.f32.f16.f16.f32 "
                "{%0,%1,%2,%3}, {%4,%5,%6,%7}, {%8,%9}, {%0,%1,%2,%3};"
                : "+f"(c0), "+f"(c1), "+f"(c2), "+f"(c3)
                : "r"(a0), "r"(a1), "r"(a2), "r"(a3), "r"(b0), "r"(b1));
        }

        // load next task's group 0 into bufA
        if (has2) {
            #pragma unroll
            for (int i = 0; i < 8; i++) bufA[i] = __ldg(wp2 + 4 * i + tq);
        }

        // ---- compute group 1 from bufB ----
        #pragma unroll
        for (int i = 0; i < 8; i++) {
            unsigned a0, a1, a2, a3;
            unsigned aaddr = smem_base + a_off + (unsigned)((k0 + 128 + i * 16) * 2);
            asm volatile(
                "ldmatrix.sync.aligned.m8n8.x4.shared.b16 {%0,%1,%2,%3}, [%4];"
                : "=r"(a0), "=r"(a1), "=r"(a2), "=r"(a3) : "r"(aaddr));

            int4 w = bufB[i];
            __half2 h01 = __halves2half2(__int2half_rn(w.x), __int2half_rn(w.y));
            __half2 h23 = __halves2half2(__int2half_rn(w.z), __int2half_rn(w.w));
            unsigned u01 = *reinterpret_cast<unsigned*>(&h01);
            unsigned u23 = *reinterpret_cast<unsigned*>(&h23);
            unsigned s1 = __shfl_sync(0xffffffffu, u01, sA);
            unsigned s2 = __shfl_sync(0xffffffffu, u23, sA);
            unsigned s3 = __shfl_sync(0xffffffffu, u01, sB);
            unsigned s4 = __shfl_sync(0xffffffffu, u23, sB);
            unsigned b0 = todd ? s2 : s1;
            unsigned b1 = todd ? s4 : s3;

            asm volatile(
                "mma.sync.aligned.m16n8k16.row.col.f32.f16.f16.f32 "
                "{%0,%1,%2,%3}, {%4,%5,%6,%7}, {%8,%9}, {%0,%1,%2,%3};"
                : "+f"(c0), "+f"(c1), "+f"(c2), "+f"(c3)
                : "r"(a0), "r"(a1), "r"(a2), "r"(a3), "r"(b0), "r"(b1));
        }

        // ---- epilogue: scale, accumulate (out already holds bias) ----
        {
            const int o0 = n * 8 + tq * 2;
            const float s0 = __ldg(scale + o0);
            const float s1f = __ldg(scale + o0 + 1);
            atomicAdd(&out[(size_t)ng * OUT_F + o0],           c0 * s0);
            atomicAdd(&out[(size_t)ng * OUT_F + o0 + 1],       c1 * s1f);
            atomicAdd(&out[(size_t)(ng + 8) * OUT_F + o0],     c2 * s0);
            atomicAdd(&out[(size_t)(ng + 8) * OUT_F + o0 + 1], c3 * s1f);
        }

        if (!has2) break;
        n  = n2;
        k0 = k02;
        wp = wp2;
    }
}

// ---------------------------------------------------------------------------
extern "C" void kernel_launch(void* const* d_in, const int* in_sizes, int n_in,
                              void* d_out, int out_size) {
    const float* x     = (const float*)d_in[0];
    const int*   w     = (const int*)  d_in[1];
    const float* scale = (const float*)d_in[2];
    const float* bias  = (const float*)d_in[3];
    float*       out   = (float*)d_out;

    cudaFuncSetAttribute(gemm_kernel,
                         cudaFuncAttributeMaxDynamicSharedMemorySize, SMEM_BYTES);

    prologue_kernel<<<344, 256>>>(x, bias, out);
    gemm_kernel<<<BLOCKS, THREADS, SMEM_BYTES>>>(w, scale, out);
}

// round 6
// speedup vs baseline: 1.2000x; 1.1476x over previous
#include <cuda_runtime.h>
#include <cuda_fp16.h>
#include <stdint.h>

#define IN_F   4096
#define OUT_F  11008
#define BATCH  16

#define K_CHUNKS 8
#define K_TASK   (IN_F / K_CHUNKS)      // 512 k per task
#define NTILES   (OUT_F / 8)            // 1376 n-tiles (8 channels)
#define NTASKS   (NTILES * K_CHUNKS)    // 11008

#define BLOCKS   148
#define THREADS  512

#define ROW_H      (IN_F + 8)           // padded row stride in halves
#define SMEM_BYTES (BATCH * ROW_H * 2)  // 131,328 B

#define KGROUP   128
#define NGROUPS  (K_TASK / KGROUP)      // 4

// g_xh holds x in PERMUTED k-order: within each 16-k block, half2-pair q
// (q = (k/2) & 7) is stored at pair position ((q&1)<<2) | (q>>1).
// This makes raw LDG.128 weight quads line up with MMA B-fragment slots.
__device__ __half   g_xh[BATCH * IN_F];
__device__ unsigned g_ticket;

// ---------------------------------------------------------------------------
// Prologue: reset ticket, x fp32 -> fp16 (permuted), out = bias.
// ---------------------------------------------------------------------------
__global__ void prologue_kernel(const float* __restrict__ x,
                                const float* __restrict__ bias,
                                float* __restrict__ out) {
    const int i      = blockIdx.x * blockDim.x + threadIdx.x;
    const int stride = gridDim.x * blockDim.x;
    if (i == 0) g_ticket = 0u;

    __half2* dst = (__half2*)g_xh;
    const int nh2 = BATCH * IN_F / 2;
    for (int j = i; j < nh2; j += stride) {
        float2 v = ((const float2*)x)[j];
        int q   = j & 7;
        int pos = (j & ~7) | ((q & 1) << 2) | (q >> 1);
        dst[pos] = __floats2half2_rn(v.x, v.y);
    }

    const float4* b4 = (const float4*)bias;
    const int total4 = BATCH * OUT_F / 4;
    const int row4   = OUT_F / 4;
    for (int j = i; j < total4; j += stride) {
        ((float4*)out)[j] = __ldg(b4 + (j % row4));
    }
}

// ---------------------------------------------------------------------------
// GEMM: persistent blocks, warp work-stealing, LDG.128 weights (no shfl —
// permutation folded into x), double-buffer + cross-task prefetch.
// Task = 8 output channels x 512 K.
// ---------------------------------------------------------------------------
extern __shared__ __half s_x[];

__global__ void __launch_bounds__(THREADS, 1)
gemm_kernel(const int* __restrict__ W,
            const float* __restrict__ scale,
            float* __restrict__ out) {
    const int tid = threadIdx.x;

    // ---- stage x (already permuted) into padded smem: straight copy ----
    {
        const uint4* src = (const uint4*)g_xh;
        const int n128 = BATCH * IN_F / 8;
        for (int i = tid; i < n128; i += THREADS) {
            int r = i >> 9, c = i & 511;
            *(uint4*)&s_x[r * ROW_H + c * 8] = src[i];
        }
    }
    __syncthreads();

    const int lane = tid & 31;
    const int ng   = lane >> 2;     // weight row within n-tile
    const int tq   = lane & 3;      // k-quad

    unsigned smem_base = (unsigned)__cvta_generic_to_shared(s_x);
    unsigned a_off = (unsigned)((lane & 15) * (ROW_H * 2) + ((lane >> 4) & 1) * 16);

    unsigned t;
    if (lane == 0) t = atomicAdd(&g_ticket, 1u);
    t = __shfl_sync(0xffffffffu, t, 0);
    if (t >= NTASKS) return;

    int n  = (int)(t % NTILES);
    int k0 = (int)(t / NTILES) * K_TASK;
    const int4* wp = (const int4*)(W + (size_t)(n * 8 + ng) * IN_F + k0);

    int4 buf[2][8];
    // prime group 0: tile i -> int4 index 4*i + tq
    #pragma unroll
    for (int i = 0; i < 8; i++) buf[0][i] = __ldg(wp + 4 * i + tq);

    for (;;) {
        // steal next task now (ATOMG latency hidden under this task)
        unsigned t2;
        if (lane == 0) t2 = atomicAdd(&g_ticket, 1u);
        t2 = __shfl_sync(0xffffffffu, t2, 0);
        const bool has2 = (t2 < NTASKS);
        int n2 = 0, k02 = 0;
        const int4* wp2 = wp;
        if (has2) {
            n2  = (int)(t2 % NTILES);
            k02 = (int)(t2 / NTILES) * K_TASK;
            wp2 = (const int4*)(W + (size_t)(n2 * 8 + ng) * IN_F + k02);
        }

        float c0 = 0.f, c1 = 0.f, c2 = 0.f, c3 = 0.f;

        #pragma unroll
        for (int g = 0; g < NGROUPS; g++) {
            const int cur = g & 1;
            const int nxt = cur ^ 1;

            // prefetch next group, or next task's group 0 on the last group
            if (g + 1 < NGROUPS) {
                const int kbase = (g + 1) * 32;      // int4s per group = 32
                #pragma unroll
                for (int i = 0; i < 8; i++)
                    buf[nxt][i] = __ldg(wp + kbase + 4 * i + tq);
            } else if (has2) {
                #pragma unroll
                for (int i = 0; i < 8; i++)
                    buf[nxt][i] = __ldg(wp2 + 4 * i + tq);
            }

            const int kk = k0 + g * KGROUP;
            #pragma unroll
            for (int i = 0; i < 8; i++) {
                unsigned a0, a1, a2, a3;
                unsigned aaddr = smem_base + a_off + (unsigned)((kk + i * 16) * 2);
                asm volatile(
                    "ldmatrix.sync.aligned.m8n8.x4.shared.b16 {%0,%1,%2,%3}, [%4];"
                    : "=r"(a0), "=r"(a1), "=r"(a2), "=r"(a3) : "r"(aaddr));

                int4 w = buf[cur][i];
                // physical k 4tq..4tq+3 == MMA slots {2tq,2tq+1} (b0),
                // {2tq+8,2tq+9} (b1) under the folded permutation.
                __half2 hb0 = __halves2half2(__int2half_rn(w.x), __int2half_rn(w.y));
                __half2 hb1 = __halves2half2(__int2half_rn(w.z), __int2half_rn(w.w));
                unsigned b0 = *reinterpret_cast<unsigned*>(&hb0);
                unsigned b1 = *reinterpret_cast<unsigned*>(&hb1);

                asm volatile(
                    "mma.sync.aligned.m16n8k16.row.col.f32.f16.f16.f32 "
                    "{%0,%1,%2,%3}, {%4,%5,%6,%7}, {%8,%9}, {%0,%1,%2,%3};"
                    : "+f"(c0), "+f"(c1), "+f"(c2), "+f"(c3)
                    : "r"(a0), "r"(a1), "r"(a2), "r"(a3), "r"(b0), "r"(b1));
            }
        }

        // ---- epilogue: scale, accumulate (out already holds bias) ----
        {
            const int o0 = n * 8 + tq * 2;
            const float s0  = __ldg(scale + o0);
            const float s1f = __ldg(scale + o0 + 1);
            atomicAdd(&out[(size_t)ng * OUT_F + o0],           c0 * s0);
            atomicAdd(&out[(size_t)ng * OUT_F + o0 + 1],       c1 * s1f);
            atomicAdd(&out[(size_t)(ng + 8) * OUT_F + o0],     c2 * s0);
            atomicAdd(&out[(size_t)(ng + 8) * OUT_F + o0 + 1], c3 * s1f);
        }

        if (!has2) break;
        n  = n2;
        k0 = k02;
        wp = wp2;
    }
}

// ---------------------------------------------------------------------------
extern "C" void kernel_launch(void* const* d_in, const int* in_sizes, int n_in,
                              void* d_out, int out_size) {
    const float* x     = (const float*)d_in[0];
    const int*   w     = (const int*)  d_in[1];
    const float* scale = (const float*)d_in[2];
    const float* bias  = (const float*)d_in[3];
    float*       out   = (float*)d_out;

    cudaFuncSetAttribute(gemm_kernel,
                         cudaFuncAttributeMaxDynamicSharedMemorySize, SMEM_BYTES);

    prologue_kernel<<<344, 256>>>(x, bias, out);
    gemm_kernel<<<BLOCKS, THREADS, SMEM_BYTES>>>(w, scale, out);
}

// round 7
// speedup vs baseline: 1.2088x; 1.0073x over previous
#include <cuda_runtime.h>
#include <cuda_fp16.h>
#include <stdint.h>

#define IN_F   4096
#define OUT_F  11008
#define BATCH  16

#define K_CHUNKS 8
#define K_TASK   (IN_F / K_CHUNKS)      // 512 k per task
#define NTILES   (OUT_F / 8)            // 1376 n-tiles (8 channels)
#define NTASKS   (NTILES * K_CHUNKS)    // 11008

#define BLOCKS   148
#define THREADS  512
#define NWARPS   (BLOCKS * THREADS / 32)  // 2368 warps

#define ROW_H      (IN_F + 8)           // padded row stride in halves
#define SMEM_BYTES (BATCH * ROW_H * 2)  // 131,328 B

#define KGROUP   128
#define NGROUPS  (K_TASK / KGROUP)      // 4

// g_xh holds x in PERMUTED k-order: within each 16-k block, half2-pair q
// (q = (k/2) & 7) is stored at pair position ((q&1)<<2) | (q>>1).
// This makes raw LDG.128 weight quads line up with MMA B-fragment slots.
__device__ __half g_xh[BATCH * IN_F];

// ---------------------------------------------------------------------------
// Prologue: x fp32 -> fp16 (permuted), out = bias.
// ---------------------------------------------------------------------------
__global__ void prologue_kernel(const float* __restrict__ x,
                                const float* __restrict__ bias,
                                float* __restrict__ out) {
    const int i      = blockIdx.x * blockDim.x + threadIdx.x;
    const int stride = gridDim.x * blockDim.x;

    __half2* dst = (__half2*)g_xh;
    const int nh2 = BATCH * IN_F / 2;
    for (int j = i; j < nh2; j += stride) {
        float2 v = ((const float2*)x)[j];
        int q   = j & 7;
        int pos = (j & ~7) | ((q & 1) << 2) | (q >> 1);
        dst[pos] = __floats2half2_rn(v.x, v.y);
    }

    const float4* b4 = (const float4*)bias;
    const int total4 = BATCH * OUT_F / 4;
    const int row4   = OUT_F / 4;
    for (int j = i; j < total4; j += stride) {
        ((float4*)out)[j] = __ldg(b4 + (j % row4));
    }
}

// ---------------------------------------------------------------------------
// GEMM: persistent blocks, STATIC interleaved task schedule (no atomics),
// LDG.128 weights (permutation folded into x), double-buffer +
// cross-task prefetch. Task = 8 output channels x 512 K.
// ---------------------------------------------------------------------------
extern __shared__ __half s_x[];

__global__ void __launch_bounds__(THREADS, 1)
gemm_kernel(const int* __restrict__ W,
            const float* __restrict__ scale,
            float* __restrict__ out) {
    const int tid = threadIdx.x;

    // ---- stage x (already permuted) into padded smem: straight copy ----
    {
        const uint4* src = (const uint4*)g_xh;
        const int n128 = BATCH * IN_F / 8;
        for (int i = tid; i < n128; i += THREADS) {
            int r = i >> 9, c = i & 511;
            *(uint4*)&s_x[r * ROW_H + c * 8] = src[i];
        }
    }
    __syncthreads();

    const int lane = tid & 31;
    const int ng   = lane >> 2;     // weight row within n-tile
    const int tq   = lane & 3;      // k-quad

    unsigned smem_base = (unsigned)__cvta_generic_to_shared(s_x);
    unsigned a_off = (unsigned)((lane & 15) * (ROW_H * 2) + ((lane >> 4) & 1) * 16);

    // static schedule: this warp's tasks are t, t+NWARPS, t+2*NWARPS, ...
    int t = blockIdx.x * (THREADS / 32) + (tid >> 5);

    int n  = t % NTILES;
    int k0 = (t / NTILES) * K_TASK;
    const int4* wp = (const int4*)(W + (size_t)(n * 8 + ng) * IN_F + k0);

    int4 buf[2][8];
    #pragma unroll
    for (int i = 0; i < 8; i++) buf[0][i] = __ldg(wp + 4 * i + tq);

    for (;;) {
        const int  tn   = t + NWARPS;
        const bool has2 = (tn < NTASKS);
        int n2 = 0, k02 = 0;
        const int4* wp2 = wp;
        if (has2) {
            n2  = tn % NTILES;
            k02 = (tn / NTILES) * K_TASK;
            wp2 = (const int4*)(W + (size_t)(n2 * 8 + ng) * IN_F + k02);
        }

        float c0 = 0.f, c1 = 0.f, c2 = 0.f, c3 = 0.f;

        #pragma unroll
        for (int g = 0; g < NGROUPS; g++) {
            const int cur = g & 1;
            const int nxt = cur ^ 1;

            // prefetch next group, or next task's group 0 on the last group
            if (g + 1 < NGROUPS) {
                const int kbase = (g + 1) * 32;      // int4s per group
                #pragma unroll
                for (int i = 0; i < 8; i++)
                    buf[nxt][i] = __ldg(wp + kbase + 4 * i + tq);
            } else if (has2) {
                #pragma unroll
                for (int i = 0; i < 8; i++)
                    buf[nxt][i] = __ldg(wp2 + 4 * i + tq);
            }

            const int kk = k0 + g * KGROUP;
            #pragma unroll
            for (int i = 0; i < 8; i++) {
                unsigned a0, a1, a2, a3;
                unsigned aaddr = smem_base + a_off + (unsigned)((kk + i * 16) * 2);
                asm volatile(
                    "ldmatrix.sync.aligned.m8n8.x4.shared.b16 {%0,%1,%2,%3}, [%4];"
                    : "=r"(a0), "=r"(a1), "=r"(a2), "=r"(a3) : "r"(aaddr));

                int4 w = buf[cur][i];
                // physical k 4tq..4tq+3 == MMA slots {2tq,2tq+1} (b0),
                // {2tq+8,2tq+9} (b1) under the folded permutation.
                __half2 hb0 = __halves2half2(__int2half_rn(w.x), __int2half_rn(w.y));
                __half2 hb1 = __halves2half2(__int2half_rn(w.z), __int2half_rn(w.w));
                unsigned b0 = *reinterpret_cast<unsigned*>(&hb0);
                unsigned b1 = *reinterpret_cast<unsigned*>(&hb1);

                asm volatile(
                    "mma.sync.aligned.m16n8k16.row.col.f32.f16.f16.f32 "
                    "{%0,%1,%2,%3}, {%4,%5,%6,%7}, {%8,%9}, {%0,%1,%2,%3};"
                    : "+f"(c0), "+f"(c1), "+f"(c2), "+f"(c3)
                    : "r"(a0), "r"(a1), "r"(a2), "r"(a3), "r"(b0), "r"(b1));
            }
        }

        // ---- epilogue: scale, accumulate (out already holds bias) ----
        {
            const int o0 = n * 8 + tq * 2;
            const float s0  = __ldg(scale + o0);
            const float s1f = __ldg(scale + o0 + 1);
            atomicAdd(&out[(size_t)ng * OUT_F + o0],           c0 * s0);
            atomicAdd(&out[(size_t)ng * OUT_F + o0 + 1],       c1 * s1f);
            atomicAdd(&out[(size_t)(ng + 8) * OUT_F + o0],     c2 * s0);
            atomicAdd(&out[(size_t)(ng + 8) * OUT_F + o0 + 1], c3 * s1f);
        }

        if (!has2) break;
        t  = tn;
        n  = n2;
        k0 = k02;
        wp = wp2;
    }
}

// ---------------------------------------------------------------------------
extern "C" void kernel_launch(void* const* d_in, const int* in_sizes, int n_in,
                              void* d_out, int out_size) {
    const float* x     = (const float*)d_in[0];
    const int*   w     = (const int*)  d_in[1];
    const float* scale = (const float*)d_in[2];
    const float* bias  = (const float*)d_in[3];
    float*       out   = (float*)d_out;

    cudaFuncSetAttribute(gemm_kernel,
                         cudaFuncAttributeMaxDynamicSharedMemorySize, SMEM_BYTES);

    prologue_kernel<<<344, 256>>>(x, bias, out);
    gemm_kernel<<<BLOCKS, THREADS, SMEM_BYTES>>>(w, scale, out);
}

// round 9
// speedup vs baseline: 1.2653x; 1.0468x over previous
#include <cuda_runtime.h>
#include <cuda_fp16.h>
#include <stdint.h>

#define IN_F   4096
#define OUT_F  11008
#define BATCH  16

#define KCH      8                      // k-chunks (one per block group)
#define K_TASK   512                    // k per task
#define NTILES   1376                   // n-tiles of 8 channels

#define BLOCKS   148
#define THREADS  288                    // 8 consumer warps + 1 producer warp
#define RING     8

#define WROW_B   2112                   // 2048 + 64 pad -> conflict-free LDS.128
#define SLOT_B   (8 * WROW_B)           // 16,896 B per ring slot
#define SLOT_TX  16384                  // actual bytes per fill (8 x 2048)
#define XROW_H   520                    // halves per x row (512 + 8 pad)

#define SMEM_MBAR 0                     // slot s: full @ s*16, empty @ s*16+8
#define SMEM_X    256
#define SMEM_W    (SMEM_X + BATCH * XROW_H * 2)   // 256 + 16640 = 16896
#define SMEM_TOT  (SMEM_W + RING * SLOT_B)        // 152,064 B

// g_xh holds x in PERMUTED k-order: within each 16-k block, half2-pair q
// (q = (k/2) & 7) sits at pair position ((q&1)<<2) | (q>>1), so a raw 16B
// weight quad (phys k 4tq..4tq+3) lines up with MMA B slots {2tq,2tq+1,2tq+8,2tq+9}.
__device__ __half g_xh[BATCH * IN_F];

// ---------------- mbarrier helpers ----------------
#define MB_INIT(addr, cnt) \
    asm volatile("mbarrier.init.shared.b64 [%0], %1;" :: "r"(addr), "r"(cnt) : "memory")
#define MB_EXPECT_TX(addr, bytes) \
    asm volatile("mbarrier.arrive.expect_tx.shared.b64 _, [%0], %1;" :: "r"(addr), "r"(bytes) : "memory")
#define MB_ARRIVE(addr) \
    asm volatile("mbarrier.arrive.shared.b64 _, [%0];" :: "r"(addr) : "memory")
#define MB_WAIT(addr, parity) do {                                            \
    unsigned _done;                                                           \
    asm volatile("{\n\t.reg .pred p;\n\t"                                     \
        "mbarrier.try_wait.parity.acquire.cta.shared::cta.b64 p, [%1], %2;\n\t" \
        "selp.b32 %0, 1, 0, p;\n\t}"                                          \
        : "=r"(_done) : "r"(addr), "r"(parity) : "memory");                   \
    while (!_done) {                                                          \
        asm volatile("{\n\t.reg .pred p;\n\t"                                 \
            "mbarrier.try_wait.parity.acquire.cta.shared::cta.b64 p, [%1], %2, 0x989680;\n\t" \
            "selp.b32 %0, 1, 0, p;\n\t}"                                      \
            : "=r"(_done) : "r"(addr), "r"(parity) : "memory");               \
    }                                                                         \
} while (0)

#define BULK_CP(dst, src, mbar) \
    asm volatile("cp.async.bulk.shared::cta.global.mbarrier::complete_tx::bytes " \
                 "[%0], [%1], %2, [%3];" \
                 :: "r"(dst), "l"(src), "n"(2048), "r"(mbar) : "memory")

// ---------------------------------------------------------------------------
// Prologue: x fp32 -> fp16 (permuted), out = bias.
// ---------------------------------------------------------------------------
__global__ void prologue_kernel(const float* __restrict__ x,
                                const float* __restrict__ bias,
                                float* __restrict__ out) {
    const int i      = blockIdx.x * blockDim.x + threadIdx.x;
    const int stride = gridDim.x * blockDim.x;

    __half2* dst = (__half2*)g_xh;
    const int nh2 = BATCH * IN_F / 2;
    for (int j = i; j < nh2; j += stride) {
        float2 v = ((const float2*)x)[j];
        int q   = j & 7;
        int pos = (j & ~7) | ((q & 1) << 2) | (q >> 1);
        dst[pos] = __floats2half2_rn(v.x, v.y);
    }

    const float4* b4 = (const float4*)bias;
    const int total4 = BATCH * OUT_F / 4;
    const int row4   = OUT_F / 4;
    for (int j = i; j < total4; j += stride) {
        ((float4*)out)[j] = __ldg(b4 + (j % row4));
    }
}

// ---------------------------------------------------------------------------
// GEMM: per-block k-chunk specialization; producer warp streams weight tasks
// into an 8-slot smem ring via cp.async.bulk; 8 consumer warps (slot w ->
// warp w) do ldmatrix + LDS.128 + cvt + mma and RED the scaled partials.
// ---------------------------------------------------------------------------
extern __shared__ char smem[];

__global__ void __launch_bounds__(THREADS, 1)
gemm_kernel(const int* __restrict__ W,
            const float* __restrict__ scale,
            float* __restrict__ out) {
    const int tid  = threadIdx.x;
    const int lane = tid & 31;
    const int wid  = tid >> 5;

    const int kc  = blockIdx.x & 7;
    const int bi  = blockIdx.x >> 3;
    const int Bkc = (kc < 4) ? 19 : 18;          // blocks sharing this kc
    const int T   = (NTILES - bi + Bkc - 1) / Bkc;  // tasks for this block

    const unsigned sb = (unsigned)__cvta_generic_to_shared(smem);

    // ---- init mbarriers ----
    if (tid == 0) {
        #pragma unroll
        for (int s = 0; s < RING; s++) {
            MB_INIT(sb + SMEM_MBAR + s * 16,     1u);   // full
            MB_INIT(sb + SMEM_MBAR + s * 16 + 8, 1u);   // empty
        }
        asm volatile("fence.proxy.async.shared::cta;" ::: "memory");
    }

    // ---- stage this block's x k-slice (16 rows x 512 halves, permuted) ----
    {
        const uint4* src = (const uint4*)g_xh;
        // 16 rows x 64 uint4 per row = 1024 uint4
        for (int i = tid; i < BATCH * (K_TASK / 8); i += THREADS) {
            int r = i >> 6, c = i & 63;
            uint4 v = src[(r * IN_F + kc * K_TASK) / 8 + c];
            *(uint4*)(smem + SMEM_X + (r * XROW_H + c * 8) * 2) = v;
        }
    }
    __syncthreads();

    if (wid == 8) {
        // ================= producer =================
        if (lane == 0) {
            for (int j = 0; j < T; j++) {
                const int slot  = j & 7;
                const int round = j >> 3;
                MB_WAIT(sb + SMEM_MBAR + slot * 16 + 8, (unsigned)((round & 1) ^ 1));
                MB_EXPECT_TX(sb + SMEM_MBAR + slot * 16, (unsigned)SLOT_TX);

                const int n = bi + j * Bkc;
                const char* src = (const char*)(W + (size_t)n * 8 * IN_F + kc * K_TASK);
                const unsigned dst = sb + SMEM_W + slot * SLOT_B;
                #pragma unroll
                for (int r = 0; r < 8; r++) {
                    BULK_CP(dst + r * WROW_B, src + (size_t)r * (IN_F * 4),
                            sb + SMEM_MBAR + slot * 16);
                }
            }
        }
        return;
    }

    // ================= consumers (warps 0..7) =================
    const int ng = lane >> 2;      // weight row within n-tile
    const int tq = lane & 3;       // k-quad

    const unsigned a_off = sb + SMEM_X +
        (unsigned)((lane & 15) * (XROW_H * 2) + ((lane >> 4) & 1) * 16);
    const char* wslot = smem + SMEM_W + wid * SLOT_B + ng * WROW_B + tq * 16;
    const unsigned full_bar  = sb + SMEM_MBAR + wid * 16;
    const unsigned empty_bar = full_bar + 8;

    int r = 0;
    for (int j = wid; j < T; j += RING, r++) {
        MB_WAIT(full_bar, (unsigned)(r & 1));

        const int n = bi + j * Bkc;
        float c0 = 0.f, c1 = 0.f, c2 = 0.f, c3 = 0.f;

        #pragma unroll 1
        for (int g = 0; g < 4; g++) {            // 4 groups of 8 k16-tiles
            #pragma unroll
            for (int i = 0; i < 8; i++) {
                const int t = g * 8 + i;
                unsigned a0, a1, a2, a3;
                asm volatile(
                    "ldmatrix.sync.aligned.m8n8.x4.shared.b16 {%0,%1,%2,%3}, [%4];"
                    : "=r"(a0), "=r"(a1), "=r"(a2), "=r"(a3)
                    : "r"(a_off + (unsigned)(t * 32)));

                int4 w = *(const int4*)(wslot + t * 64);
                __half2 hb0 = __halves2half2(__int2half_rn(w.x), __int2half_rn(w.y));
                __half2 hb1 = __halves2half2(__int2half_rn(w.z), __int2half_rn(w.w));
                unsigned b0 = *reinterpret_cast<unsigned*>(&hb0);
                unsigned b1 = *reinterpret_cast<unsigned*>(&hb1);

                asm volatile(
                    "mma.sync.aligned.m16n8k16.row.col.f32.f16.f16.f32 "
                    "{%0,%1,%2,%3}, {%4,%5,%6,%7}, {%8,%9}, {%0,%1,%2,%3};"
                    : "+f"(c0), "+f"(c1), "+f"(c2), "+f"(c3)
                    : "r"(a0), "r"(a1), "r"(a2), "r"(a3), "r"(b0), "r"(b1));
            }
        }

        __syncwarp();
        if (lane == 0) MB_ARRIVE(empty_bar);

        // ---- epilogue: scale, accumulate (out already holds bias) ----
        const int o0 = n * 8 + tq * 2;
        const float s0  = __ldg(scale + o0);
        const float s1f = __ldg(scale + o0 + 1);
        atomicAdd(&out[(size_t)ng * OUT_F + o0],           c0 * s0);
        atomicAdd(&out[(size_t)ng * OUT_F + o0 + 1],       c1 * s1f);
        atomicAdd(&out[(size_t)(ng + 8) * OUT_F + o0],     c2 * s0);
        atomicAdd(&out[(size_t)(ng + 8) * OUT_F + o0 + 1], c3 * s1f);
    }
}

// ---------------------------------------------------------------------------
extern "C" void kernel_launch(void* const* d_in, const int* in_sizes, int n_in,
                              void* d_out, int out_size) {
    const float* x     = (const float*)d_in[0];
    const int*   w     = (const int*)  d_in[1];
    const float* scale = (const float*)d_in[2];
    const float* bias  = (const float*)d_in[3];
    float*       out   = (float*)d_out;

    cudaFuncSetAttribute(gemm_kernel,
                         cudaFuncAttributeMaxDynamicSharedMemorySize, SMEM_TOT);

    prologue_kernel<<<344, 256>>>(x, bias, out);
    gemm_kernel<<<BLOCKS, THREADS, SMEM_TOT>>>(w, scale, out);
}